// round 3
// baseline (speedup 1.0000x reference)
#include <cuda_runtime.h>
#include <math.h>

#define DIMC   96
#define NHEADS 3
#define HD     32
#define NTOK   49
#define PITCH  100
#define NTHR   192
// smem layout (floats): xs 64*100 | ws 96*100 | ks 49*100 | vs 49*100 | wb 96
#define SMEM_FLOATS 25896
#define SMEM_BYTES  (SMEM_FLOATS * 4)

typedef unsigned long long u64;

// packed fp32x2 FMA: d = a*b + d (elementwise on 2 packed floats)
__device__ __forceinline__ void fma2(u64& d, u64 a, u64 b) {
    asm("fma.rn.f32x2 %0, %1, %2, %0;" : "+l"(d) : "l"(a), "l"(b));
}
__device__ __forceinline__ u64 add2(u64 a, u64 b) {
    u64 d; asm("add.rn.f32x2 %0, %1, %2;" : "=l"(d) : "l"(a), "l"(b)); return d;
}
__device__ __forceinline__ float hsum2(u64 v) {
    float lo, hi; asm("mov.b64 {%0, %1}, %2;" : "=f"(lo), "=f"(hi) : "l"(v));
    return lo + hi;
}
__device__ __forceinline__ u64 dup2(float x) {
    u64 r; asm("mov.b64 %0, {%1, %1};" : "=l"(r) : "f"(x)); return r;
}
__device__ __forceinline__ void upk2(u64 v, float& lo, float& hi) {
    asm("mov.b64 {%0, %1}, %2;" : "=f"(lo), "=f"(hi) : "l"(v));
}

__device__ float g_bias[NHEADS * NTOK * NTOK];

__global__ void bias_precompute(const float* __restrict__ rpb,
                                const int* __restrict__ rel) {
    int i = blockIdx.x * blockDim.x + threadIdx.x;
    if (i < NTOK * NTOK) {
        int idx = rel[i];
        #pragma unroll
        for (int h = 0; h < NHEADS; ++h)
            g_bias[h * (NTOK * NTOK) + i] = rpb[idx * NHEADS + h];
    }
}

// 96-deep dot product: xr2[24 pairs... 48 u64] . w-row (smem), 4 indep chains
__device__ __forceinline__ float dot96(const u64* __restrict__ xr2,
                                       const float* __restrict__ wrow_f) {
    const ulonglong2* wrow = reinterpret_cast<const ulonglong2*>(wrow_f);
    u64 a0 = 0, a1 = 0, a2 = 0, a3 = 0;
    #pragma unroll
    for (int j = 0; j < 24; j += 2) {
        ulonglong2 w2 = wrow[j];        // 16B LDS (broadcast within warp)
        fma2(a0, xr2[2*j],     w2.x);
        fma2(a1, xr2[2*j + 1], w2.y);
        ulonglong2 w3 = wrow[j + 1];
        fma2(a2, xr2[2*j + 2], w3.x);
        fma2(a3, xr2[2*j + 3], w3.y);
    }
    return hsum2(add2(add2(a0, a1), add2(a2, a3)));
}

__global__ void __launch_bounds__(NTHR, 2)
win_attn_kernel(const float* __restrict__ x,
                const float* __restrict__ mask,
                const float* __restrict__ qkv_w,
                const float* __restrict__ qkv_b,
                const float* __restrict__ proj_w,
                const float* __restrict__ proj_b,
                float* __restrict__ out) {
    extern __shared__ float sm[];
    float* xs = sm;          // 64 x PITCH : x tile, later attention output O
    float* ws = sm + 6400;   // 96 x PITCH : weight staging
    float* ks = sm + 16000;  // 49 x PITCH : k tile, later output staging
    float* vs = sm + 20900;  // 49 x PITCH : v tile
    float* wb = sm + 25800;  // 96 : bias staging

    const int b   = blockIdx.x;
    const int wi  = b & 63;
    const int tid = threadIdx.x;
    const int n   = tid & 63;        // token row (49 valid, padded to 64)
    const int g   = tid >> 6;        // column group / head (0..2)
    const bool rowok = (n < NTOK);

    // ---- Phase 0: stage x tile (coalesced), zero pad rows ----
    const float* xg = x + (size_t)b * (NTOK * DIMC);
    for (int i = tid; i < NTOK * DIMC; i += NTHR)
        xs[(i / DIMC) * PITCH + (i % DIMC)] = xg[i];
    for (int i = tid; i < (64 - NTOK) * DIMC; i += NTHR)
        xs[(NTOK + i / DIMC) * PITCH + (i % DIMC)] = 0.0f;
    __syncthreads();

    // x row -> packed registers (48 u64 = 96 floats)
    u64 xr2[48];
    {
        const ulonglong2* xrow = reinterpret_cast<const ulonglong2*>(xs + n * PITCH);
        #pragma unroll
        for (int j = 0; j < 24; ++j) {
            ulonglong2 t = xrow[j];
            xr2[2*j] = t.x; xr2[2*j + 1] = t.y;
        }
    }

    // ---- Phase 1a: Q slice -> packed registers (head g of row n) ----
    u64 q2[16];   // 32 floats, pre-scaled
    {
        for (int i = tid; i < DIMC * DIMC; i += NTHR)
            ws[(i / DIMC) * PITCH + (i % DIMC)] = qkv_w[i];
        if (tid < DIMC) wb[tid] = qkv_b[tid];
        __syncthreads();
        const float scale = 0.17677669529663687f; // 32^-0.5
        #pragma unroll 2
        for (int cl = 0; cl < HD; cl += 2) {
            const int c = g * HD + cl;
            float v0 = (dot96(xr2, ws + c * PITCH) + wb[c]) * scale;
            float v1 = (dot96(xr2, ws + (c + 1) * PITCH) + wb[c + 1]) * scale;
            asm("mov.b64 %0, {%1, %2};" : "=l"(q2[cl >> 1]) : "f"(v0), "f"(v1));
        }
        __syncthreads();
    }

    // ---- Phase 1b: K and V slices -> smem ----
    for (int s = 1; s < 3; ++s) {
        const float* wg = qkv_w + s * DIMC * DIMC;
        for (int i = tid; i < DIMC * DIMC; i += NTHR)
            ws[(i / DIMC) * PITCH + (i % DIMC)] = wg[i];
        if (tid < DIMC) wb[tid] = qkv_b[s * DIMC + tid];
        __syncthreads();
        float* dst = (s == 1) ? ks : vs;
        #pragma unroll 2
        for (int cl = 0; cl < HD; ++cl) {
            const int c = g * HD + cl;
            float acc = dot96(xr2, ws + c * PITCH) + wb[c];
            if (rowok) dst[n * PITCH + c] = acc;
        }
        __syncthreads();
    }

    // ---- Phase 2+3: logits, neg-softmax, A@V ----
    const int h = g;
    if (rowok) {
        float lg[NTOK];
        const float* brow = g_bias + h * (NTOK * NTOK) + n * NTOK;
        const float* mrow = mask + ((size_t)wi * NTOK + n) * NTOK;
        #pragma unroll 7
        for (int m = 0; m < NTOK; ++m) {
            const ulonglong2* krow =
                reinterpret_cast<const ulonglong2*>(ks + m * PITCH + h * HD);
            u64 a0 = 0, a1 = 0, a2 = 0, a3 = 0;
            #pragma unroll
            for (int j = 0; j < 8; j += 2) {
                ulonglong2 k2 = krow[j];
                fma2(a0, q2[2*j],     k2.x);
                fma2(a1, q2[2*j + 1], k2.y);
                ulonglong2 k3 = krow[j + 1];
                fma2(a2, q2[2*j + 2], k3.x);
                fma2(a3, q2[2*j + 3], k3.y);
            }
            lg[m] = hsum2(add2(add2(a0, a1), add2(a2, a3))) + brow[m] + mrow[m];
        }
        // neg softmax: sign(l) * softmax(|l|), max-subtracted
        float M = 0.0f;
        #pragma unroll
        for (int m = 0; m < NTOK; ++m) M = fmaxf(M, fabsf(lg[m]));
        float ssum = 0.0f;
        #pragma unroll
        for (int m = 0; m < NTOK; ++m) {
            float l = lg[m];
            float e = __expf(fabsf(l) - M);
            ssum += e;
            lg[m] = (l > 0.0f) ? e : ((l < 0.0f) ? -e : 0.0f);
        }
        const float rinv = 1.0f / ssum;

        u64 oacc[16];   // 32 floats packed
        #pragma unroll
        for (int j = 0; j < 16; ++j) oacc[j] = 0;
        #pragma unroll 7
        for (int m = 0; m < NTOK; ++m) {
            const u64 p2 = dup2(lg[m]);
            const ulonglong2* vrow =
                reinterpret_cast<const ulonglong2*>(vs + m * PITCH + h * HD);
            #pragma unroll
            for (int j = 0; j < 8; ++j) {
                ulonglong2 v2 = vrow[j];
                fma2(oacc[2*j],     p2, v2.x);
                fma2(oacc[2*j + 1], p2, v2.y);
            }
        }
        float2* orow = reinterpret_cast<float2*>(xs + n * PITCH + h * HD);
        #pragma unroll
        for (int j = 0; j < 16; ++j) {
            float lo, hi; upk2(oacc[j], lo, hi);
            float2 o2; o2.x = lo * rinv; o2.y = hi * rinv;
            orow[j] = o2;
        }
    }
    __syncthreads();

    // ---- Phase 4: projection. O rows are in xs (pad rows still zero). ----
    for (int i = tid; i < DIMC * DIMC; i += NTHR)
        ws[(i / DIMC) * PITCH + (i % DIMC)] = proj_w[i];
    if (tid < DIMC) wb[tid] = proj_b[tid];
    __syncthreads();

    // reload O row packed
    u64 or2[48];
    {
        const ulonglong2* xrow = reinterpret_cast<const ulonglong2*>(xs + n * PITCH);
        #pragma unroll
        for (int j = 0; j < 24; ++j) {
            ulonglong2 t = xrow[j];
            or2[2*j] = t.x; or2[2*j + 1] = t.y;
        }
    }
    #pragma unroll 2
    for (int cl = 0; cl < HD; ++cl) {
        const int c = g * HD + cl;
        float acc = dot96(or2, ws + c * PITCH) + wb[c];
        if (rowok) ks[n * PITCH + c] = acc;
    }
    __syncthreads();

    // ---- Phase 5: coalesced store ----
    float* og = out + (size_t)b * (NTOK * DIMC);
    for (int i = tid; i < NTOK * DIMC; i += NTHR)
        og[i] = ks[(i / DIMC) * PITCH + (i % DIMC)];
}

extern "C" void kernel_launch(void* const* d_in, const int* in_sizes, int n_in,
                              void* d_out, int out_size) {
    const float* x      = (const float*)d_in[0];
    const float* mask   = (const float*)d_in[1];
    const float* qkv_w  = (const float*)d_in[2];
    const float* qkv_b  = (const float*)d_in[3];
    const float* proj_w = (const float*)d_in[4];
    const float* proj_b = (const float*)d_in[5];
    const float* rpb    = (const float*)d_in[6];
    const int*   rel    = (const int*)d_in[7];
    float* out = (float*)d_out;

    cudaFuncSetAttribute(win_attn_kernel,
                         cudaFuncAttributeMaxDynamicSharedMemorySize, SMEM_BYTES);

    bias_precompute<<<(NTOK * NTOK + 127) / 128, 128>>>(rpb, rel);
    win_attn_kernel<<<4096, NTHR, SMEM_BYTES>>>(x, mask, qkv_w, qkv_b,
                                                proj_w, proj_b, out);
}

// round 4
// speedup vs baseline: 1.5132x; 1.5132x over previous
#include <cuda_runtime.h>
#include <math.h>

#define DIMC   96
#define NTOK   49
#define PITCH  100
#define NTHR   192

// smem layout (floats)
#define XS_OFF 0        // 64 x PITCH : x tile, later attention output O
#define QS_OFF 6400     // 49 x PITCH : q
#define KS_OFF 11300    // 49 x PITCH : k
#define VS_OFF 16200    // 49 x PITCH : v
#define SMEM_FLOATS 21100
#define SMEM_BYTES  (SMEM_FLOATS * 4)

typedef unsigned long long u64;
typedef unsigned int u32;

__device__ float  g_bias[3 * NTOK * NTOK];
// [phase(4)][ks(12)][nbg(12)][lane(32)] -> (b0hi, b1hi, b0lo, b1lo)
__device__ float4 g_wfrag[4 * 12 * 12 * 32];

__device__ __forceinline__ float tf32r(float a) {
    float r; asm("cvt.rna.tf32.f32 %0, %1;" : "=f"(r) : "f"(a)); return r;
}

// ---- packed fp32x2 helpers (attention core) ----
__device__ __forceinline__ void fma2(u64& d, u64 a, u64 b) {
    asm("fma.rn.f32x2 %0, %1, %2, %0;" : "+l"(d) : "l"(a), "l"(b));
}
__device__ __forceinline__ u64 add2(u64 a, u64 b) {
    u64 d; asm("add.rn.f32x2 %0, %1, %2;" : "=l"(d) : "l"(a), "l"(b)); return d;
}
__device__ __forceinline__ float hsum2(u64 v) {
    float lo, hi; asm("mov.b64 {%0, %1}, %2;" : "=f"(lo), "=f"(hi) : "l"(v));
    return lo + hi;
}
__device__ __forceinline__ u64 dup2(float x) {
    u64 r; asm("mov.b64 %0, {%1, %1};" : "=l"(r) : "f"(x)); return r;
}
__device__ __forceinline__ void upk2(u64 v, float& lo, float& hi) {
    asm("mov.b64 {%0, %1}, %2;" : "=f"(lo), "=f"(hi) : "l"(v));
}

// ---- m16n8k8 tf32 mma, D = A*B + D ----
__device__ __forceinline__ void mma8(float c[4], const u32 a[4], u32 b0, u32 b1) {
    asm volatile(
        "mma.sync.aligned.m16n8k8.row.col.f32.tf32.tf32.f32 "
        "{%0,%1,%2,%3}, {%4,%5,%6,%7}, {%8,%9}, {%0,%1,%2,%3};"
        : "+f"(c[0]), "+f"(c[1]), "+f"(c[2]), "+f"(c[3])
        : "r"(a[0]), "r"(a[1]), "r"(a[2]), "r"(a[3]), "r"(b0), "r"(b1));
}

// ---- prep: gather rpb bias + split weights into tf32 hi/lo fragment order ----
__global__ void prep_kernel(const float* __restrict__ rpb,
                            const int* __restrict__ rel,
                            const float* __restrict__ qkv_w,
                            const float* __restrict__ proj_w) {
    int i = blockIdx.x * blockDim.x + threadIdx.x;
    if (i < NTOK * NTOK) {
        int idx = rel[i];
        #pragma unroll
        for (int h = 0; h < 3; ++h)
            g_bias[h * (NTOK * NTOK) + i] = rpb[idx * 3 + h];
    }
    if (i < 4 * 12 * 12 * 32) {
        int lane = i & 31;
        int rest = i >> 5;          // 0..575
        int nbg  = rest % 12;
        int ks   = (rest / 12) % 12;
        int p    = rest / 144;      // 0..3
        const float* W = (p < 3) ? (qkv_w + p * DIMC * DIMC) : proj_w;
        int g = lane >> 2, t = lane & 3;
        int n = nbg * 8 + g;
        int k0 = ks * 8 + t;
        float b0 = W[n * DIMC + k0];
        float b1 = W[n * DIMC + k0 + 4];
        float h0 = tf32r(b0), h1 = tf32r(b1);
        float4 v;
        v.x = h0; v.y = h1;
        v.z = tf32r(b0 - h0); v.w = tf32r(b1 - h1);
        g_wfrag[i] = v;
    }
}

// ---- one 64x96x96 GEMM on tensor cores (3xTF32), per-CTA ----
__device__ __forceinline__ void gemm64x96(
    const float* __restrict__ xsA,     // A tile 64 x PITCH (smem)
    int slice,                          // 0..3 -> g_wfrag phase
    const float* __restrict__ bias,     // 96 biases (gmem)
    float scale,
    float* __restrict__ dst_smem,       // 49 x PITCH, or null
    float* __restrict__ dst_gmem,       // rows<49, ld 96, or null
    int wm, int wn, int g, int t, int lane) {

    float acc[2][4][4];
    #pragma unroll
    for (int a = 0; a < 2; ++a)
        #pragma unroll
        for (int b = 0; b < 4; ++b)
            #pragma unroll
            for (int c = 0; c < 4; ++c) acc[a][b][c] = 0.0f;

    const float4* wf = g_wfrag + slice * (12 * 12 * 32);

    float4 bpre[4];
    #pragma unroll
    for (int nb = 0; nb < 4; ++nb)
        bpre[nb] = wf[(wn * 4 + nb) * 32 + lane];

    #pragma unroll 2
    for (int ks = 0; ks < 12; ++ks) {
        float4 bcur[4];
        #pragma unroll
        for (int nb = 0; nb < 4; ++nb) bcur[nb] = bpre[nb];
        if (ks < 11) {
            #pragma unroll
            for (int nb = 0; nb < 4; ++nb)
                bpre[nb] = wf[((ks + 1) * 12 + wn * 4 + nb) * 32 + lane];
        }
        // A fragments: rows (wm*32+mb*16)+{g, g+8}, cols ks*8+{t, t+4}
        u32 ah[2][4], al[2][4];
        #pragma unroll
        for (int mb = 0; mb < 2; ++mb) {
            const int r = wm * 32 + mb * 16 + g;
            const float* xp = xsA + ks * 8 + t;
            float a0 = xp[r * PITCH];
            float a1 = xp[(r + 8) * PITCH];
            float a2 = xp[r * PITCH + 4];
            float a3 = xp[(r + 8) * PITCH + 4];
            float h;
            h = tf32r(a0); ah[mb][0] = __float_as_uint(h); al[mb][0] = __float_as_uint(tf32r(a0 - h));
            h = tf32r(a1); ah[mb][1] = __float_as_uint(h); al[mb][1] = __float_as_uint(tf32r(a1 - h));
            h = tf32r(a2); ah[mb][2] = __float_as_uint(h); al[mb][2] = __float_as_uint(tf32r(a2 - h));
            h = tf32r(a3); ah[mb][3] = __float_as_uint(h); al[mb][3] = __float_as_uint(tf32r(a3 - h));
        }
        #pragma unroll
        for (int nb = 0; nb < 4; ++nb) {
            u32 b0h = __float_as_uint(bcur[nb].x), b1h = __float_as_uint(bcur[nb].y);
            u32 b0l = __float_as_uint(bcur[nb].z), b1l = __float_as_uint(bcur[nb].w);
            #pragma unroll
            for (int mb = 0; mb < 2; ++mb) {
                mma8(acc[mb][nb], ah[mb], b0h, b1h);   // hi*hi
                mma8(acc[mb][nb], ah[mb], b0l, b1l);   // hi*lo
                mma8(acc[mb][nb], al[mb], b0h, b1h);   // lo*hi
            }
        }
    }

    // epilogue: bias add, optional scale, guarded stores (rows < 49)
    #pragma unroll
    for (int mb = 0; mb < 2; ++mb) {
        #pragma unroll
        for (int nb = 0; nb < 4; ++nb) {
            const int r0 = wm * 32 + mb * 16 + g;
            const int c0 = wn * 32 + nb * 8 + (t << 1);
            float bx = bias[c0], by = bias[c0 + 1];
            float v00 = (acc[mb][nb][0] + bx) * scale;
            float v01 = (acc[mb][nb][1] + by) * scale;
            float v10 = (acc[mb][nb][2] + bx) * scale;
            float v11 = (acc[mb][nb][3] + by) * scale;
            if (dst_smem) {
                if (r0 < NTOK)     { dst_smem[r0 * PITCH + c0] = v00; dst_smem[r0 * PITCH + c0 + 1] = v01; }
                if (r0 + 8 < NTOK) { dst_smem[(r0 + 8) * PITCH + c0] = v10; dst_smem[(r0 + 8) * PITCH + c0 + 1] = v11; }
            } else {
                if (r0 < NTOK) {
                    float2 o; o.x = v00; o.y = v01;
                    *reinterpret_cast<float2*>(dst_gmem + r0 * DIMC + c0) = o;
                }
                if (r0 + 8 < NTOK) {
                    float2 o; o.x = v10; o.y = v11;
                    *reinterpret_cast<float2*>(dst_gmem + (r0 + 8) * DIMC + c0) = o;
                }
            }
        }
    }
}

__global__ void __launch_bounds__(NTHR, 2)
win_attn_kernel(const float* __restrict__ x,
                const float* __restrict__ mask,
                const float* __restrict__ qkv_b,
                const float* __restrict__ proj_b,
                float* __restrict__ out) {
    extern __shared__ float sm[];
    float* xs  = sm + XS_OFF;   // x tile / O tile
    float* qsm = sm + QS_OFF;
    float* ksm = sm + KS_OFF;
    float* vsm = sm + VS_OFF;

    const int b    = blockIdx.x;
    const int wi   = b & 63;
    const int tid  = threadIdx.x;
    const int wid  = tid >> 5;
    const int lane = tid & 31;
    const int g    = lane >> 2;
    const int t    = lane & 3;
    const int wm   = wid & 1;      // 0..1
    const int wn   = wid >> 1;     // 0..2

    // ---- stage x (64 rows: 49 real + 15 zero) ----
    const float* xg = x + (size_t)b * (NTOK * DIMC);
    for (int i = tid; i < NTOK * DIMC; i += NTHR)
        xs[(i / DIMC) * PITCH + (i % DIMC)] = xg[i];
    for (int i = tid; i < 15 * DIMC; i += NTHR)
        xs[(NTOK + i / DIMC) * PITCH + (i % DIMC)] = 0.0f;
    __syncthreads();

    // ---- q, k, v GEMMs (tensor cores) ----
    const float scale = 0.17677669529663687f;  // 32^-0.5
    gemm64x96(xs, 0, qkv_b,       scale, qsm, nullptr, wm, wn, g, t, lane);
    gemm64x96(xs, 1, qkv_b + 96,  1.0f,  ksm, nullptr, wm, wn, g, t, lane);
    gemm64x96(xs, 2, qkv_b + 192, 1.0f,  vsm, nullptr, wm, wn, g, t, lane);
    __syncthreads();

    // ---- attention: scalar fp32, thread (n, h) owns one query row ----
    const int n = tid & 63;
    const int h = tid >> 6;
    if (n < NTOK) {
        // q row -> packed regs
        u64 q2[16];
        {
            const ulonglong2* qrow =
                reinterpret_cast<const ulonglong2*>(qsm + n * PITCH + h * 32);
            #pragma unroll
            for (int j = 0; j < 8; ++j) {
                ulonglong2 tq = qrow[j];
                q2[2*j] = tq.x; q2[2*j + 1] = tq.y;
            }
        }
        float lg[NTOK];
        const float* brow = g_bias + h * (NTOK * NTOK) + n * NTOK;
        const float* mrow = mask + ((size_t)wi * NTOK + n) * NTOK;
        #pragma unroll 7
        for (int m = 0; m < NTOK; ++m) {
            const ulonglong2* krow =
                reinterpret_cast<const ulonglong2*>(ksm + m * PITCH + h * 32);
            u64 a0 = 0, a1 = 0, a2 = 0, a3 = 0;
            #pragma unroll
            for (int j = 0; j < 8; j += 2) {
                ulonglong2 k2 = krow[j];
                fma2(a0, q2[2*j],     k2.x);
                fma2(a1, q2[2*j + 1], k2.y);
                ulonglong2 k3 = krow[j + 1];
                fma2(a2, q2[2*j + 2], k3.x);
                fma2(a3, q2[2*j + 3], k3.y);
            }
            lg[m] = hsum2(add2(add2(a0, a1), add2(a2, a3))) + brow[m] + mrow[m];
        }
        // neg softmax: sign(l) * softmax(|l|)
        float M = 0.0f;
        #pragma unroll
        for (int m = 0; m < NTOK; ++m) M = fmaxf(M, fabsf(lg[m]));
        float ssum = 0.0f;
        #pragma unroll
        for (int m = 0; m < NTOK; ++m) {
            float l = lg[m];
            float e = __expf(fabsf(l) - M);
            ssum += e;
            lg[m] = (l > 0.0f) ? e : ((l < 0.0f) ? -e : 0.0f);
        }
        const float rinv = 1.0f / ssum;

        u64 oacc[16];
        #pragma unroll
        for (int j = 0; j < 16; ++j) oacc[j] = 0;
        #pragma unroll 7
        for (int m = 0; m < NTOK; ++m) {
            const u64 p2 = dup2(lg[m]);
            const ulonglong2* vrow =
                reinterpret_cast<const ulonglong2*>(vsm + m * PITCH + h * 32);
            #pragma unroll
            for (int j = 0; j < 8; ++j) {
                ulonglong2 v2 = vrow[j];
                fma2(oacc[2*j],     p2, v2.x);
                fma2(oacc[2*j + 1], p2, v2.y);
            }
        }
        float2* orow = reinterpret_cast<float2*>(xs + n * PITCH + h * 32);
        #pragma unroll
        for (int j = 0; j < 16; ++j) {
            float lo, hi; upk2(oacc[j], lo, hi);
            float2 o2; o2.x = lo * rinv; o2.y = hi * rinv;
            orow[j] = o2;
        }
    }
    __syncthreads();

    // ---- projection (tensor cores), direct store to gmem ----
    gemm64x96(xs, 3, proj_b, 1.0f, nullptr, out + (size_t)b * (NTOK * DIMC),
              wm, wn, g, t, lane);
}

extern "C" void kernel_launch(void* const* d_in, const int* in_sizes, int n_in,
                              void* d_out, int out_size) {
    const float* x      = (const float*)d_in[0];
    const float* mask   = (const float*)d_in[1];
    const float* qkv_w  = (const float*)d_in[2];
    const float* qkv_b  = (const float*)d_in[3];
    const float* proj_w = (const float*)d_in[4];
    const float* proj_b = (const float*)d_in[5];
    const float* rpb    = (const float*)d_in[6];
    const int*   rel    = (const int*)d_in[7];
    float* out = (float*)d_out;

    cudaFuncSetAttribute(win_attn_kernel,
                         cudaFuncAttributeMaxDynamicSharedMemorySize, SMEM_BYTES);

    prep_kernel<<<144, 128>>>(rpb, rel, qkv_w, proj_w);
    win_attn_kernel<<<4096, NTHR, SMEM_BYTES>>>(x, mask, qkv_b, proj_b, out);
}